// round 2
// baseline (speedup 1.0000x reference)
#include <cuda_runtime.h>
#include <math.h>

// Problem constants (B=4, S=2048, H=128, NH=8)
#define HB 4
#define SEQ 2048
#define HD 128
#define NH 8
#define HEADS (HB * NH)            // 32
#define HEADELEMS (SEQ * HD)       // 262144
#define YELEMS (HB * SEQ * NH * HD) // 8388608

// Scratch (device globals: allocation-free per harness rules)
__device__ float g_q[YELEMS];
__device__ float g_k[YELEMS];
__device__ float g_v[YELEMS];
__device__ float g_o[YELEMS];

// ---------------------------------------------------------------------------
// Generic fp32 SGEMM: C[M,N] = A[M,K] @ B[K,N], row-major with leading dims.
// 256 threads, thread grid 16x16, microtile TM x TN split into 4-wide groups.
// Register-prefetch software pipeline over BK tiles.
// ---------------------------------------------------------------------------
template<int BM, int BN, int BK, int TM, int TN>
__global__ __launch_bounds__(256, 1)
void sgemm_kernel(int M, int N, int K,
                  const float* __restrict__ A, int lda,
                  const float* __restrict__ B, int ldb,
                  float* __restrict__ C, int ldc)
{
    __shared__ float As[BK][BM];   // stored transposed (k-major)
    __shared__ float Bs[BK][BN];

    const int tid = threadIdx.x;
    const int tx = tid & 15;
    const int ty = tid >> 4;
    const int row0 = blockIdx.y * BM;
    const int col0 = blockIdx.x * BN;

    constexpr int AE = (BM * BK) / 256;
    constexpr int BE = (BK * BN) / 256;
    constexpr int RG = TM / 4;
    constexpr int CG = TN / 4;

    float aReg[AE], bReg[BE];
    const float* Ab = A + (long)row0 * lda;
    const float* Bp = B + col0;

    // prologue: load k-tile 0 into registers
    #pragma unroll
    for (int i = 0; i < AE; i++) {
        int idx = i * 256 + tid;
        aReg[i] = Ab[(idx / BK) * lda + (idx % BK)];
    }
    #pragma unroll
    for (int i = 0; i < BE; i++) {
        int idx = i * 256 + tid;
        bReg[i] = Bp[(idx / BN) * ldb + (idx % BN)];
    }

    float acc[TM][TN];
    #pragma unroll
    for (int i = 0; i < TM; i++) {
        #pragma unroll
        for (int j = 0; j < TN; j++) acc[i][j] = 0.0f;
    }

    const int nk = K / BK;
    for (int kt = 0; kt < nk; kt++) {
        __syncthreads();
        #pragma unroll
        for (int i = 0; i < AE; i++) {
            int idx = i * 256 + tid;
            As[idx % BK][idx / BK] = aReg[i];
        }
        #pragma unroll
        for (int i = 0; i < BE; i++) {
            int idx = i * 256 + tid;
            Bs[idx / BN][idx % BN] = bReg[i];
        }
        __syncthreads();

        if (kt + 1 < nk) {  // prefetch next tile into registers
            const int k0 = (kt + 1) * BK;
            #pragma unroll
            for (int i = 0; i < AE; i++) {
                int idx = i * 256 + tid;
                aReg[i] = Ab[(idx / BK) * lda + k0 + (idx % BK)];
            }
            #pragma unroll
            for (int i = 0; i < BE; i++) {
                int idx = i * 256 + tid;
                bReg[i] = Bp[(k0 + idx / BN) * ldb + (idx % BN)];
            }
        }

        #pragma unroll
        for (int kk = 0; kk < BK; kk++) {
            float av[TM], bv[TN];
            #pragma unroll
            for (int g = 0; g < RG; g++) {
                float4 t = *(const float4*)&As[kk][g * (BM / 2) + ty * 4];
                av[g*4+0] = t.x; av[g*4+1] = t.y; av[g*4+2] = t.z; av[g*4+3] = t.w;
            }
            #pragma unroll
            for (int g = 0; g < CG; g++) {
                float4 t = *(const float4*)&Bs[kk][g * (BN / 2) + tx * 4];
                bv[g*4+0] = t.x; bv[g*4+1] = t.y; bv[g*4+2] = t.z; bv[g*4+3] = t.w;
            }
            #pragma unroll
            for (int i = 0; i < TM; i++) {
                #pragma unroll
                for (int j = 0; j < TN; j++) {
                    acc[i][j] += av[i] * bv[j];
                }
            }
        }
    }

    // epilogue (vectorized stores)
    #pragma unroll
    for (int i = 0; i < TM; i++) {
        const int row = row0 + (i / 4) * (BM / 2) + ty * 4 + (i % 4);
        #pragma unroll
        for (int g = 0; g < CG; g++) {
            const int col = col0 + g * (BN / 2) + tx * 4;
            float4 t = make_float4(acc[i][g*4+0], acc[i][g*4+1],
                                   acc[i][g*4+2], acc[i][g*4+3]);
            *(float4*)&C[(long)row * ldc + col] = t;
        }
    }
}

// ---------------------------------------------------------------------------
// Flash attention (fp32, causal) on one head chunk [2048,128].
// BQ=128 query rows per CTA, BKV=64 keys per inner tile, 256 threads.
// Q/K smem tiles use a 16B-granule XOR swizzle so the S-phase float4 operand
// loads are bank-conflict free; V/P are row-major.
// ---------------------------------------------------------------------------
#define BQ 128
#define BKV 64
#define PS_LD 68

__device__ __forceinline__ int swz(int r, int c) {
    int ch = (c >> 2) ^ ((r >> 2) & 7);
    return r * HD + ch * 4 + (c & 3);
}

__global__ __launch_bounds__(256, 1)
void flash_kernel(const float* __restrict__ gq, const float* __restrict__ gk,
                  const float* __restrict__ gv, float* __restrict__ go)
{
    extern __shared__ float smem[];
    float* Qs = smem;                 // BQ  x HD (swizzled)
    float* Ks = Qs + BQ * HD;         // BKV x HD (swizzled)
    float* Vs = Ks + BKV * HD;        // BKV x HD (row-major)
    float* Ps = Vs + BKV * HD;        // BQ  x PS_LD

    const int tid = threadIdx.x;
    const int tx = tid & 15;
    const int ty = tid >> 4;
    const int hb = blockIdx.x;                         // head 0..31
    const int qt = (int)gridDim.y - 1 - (int)blockIdx.y; // big q-tiles first
    const int q0 = qt * BQ;

    const float* Q = gq + (long)hb * HEADELEMS;
    const float* K = gk + (long)hb * HEADELEMS;
    const float* V = gv + (long)hb * HEADELEMS;
    float*       O = go + (long)hb * HEADELEMS;

    // load Q tile (16 passes x 256 threads x float4)
    #pragma unroll
    for (int p = 0; p < (BQ * HD) / (256 * 4); p++) {
        int idx = p * 256 + tid;
        int r = idx >> 5;
        int c = (idx & 31) * 4;
        float4 t = *(const float4*)&Q[(q0 + r) * HD + c];
        *(float4*)&Qs[swz(r, c)] = t;
    }

    float accO[8][8];
    #pragma unroll
    for (int i = 0; i < 8; i++) {
        #pragma unroll
        for (int j = 0; j < 8; j++) accO[i][j] = 0.0f;
    }
    float m_i[8], l_i[8];
    #pragma unroll
    for (int i = 0; i < 8; i++) { m_i[i] = -INFINITY; l_i[i] = 0.0f; }

    const float scale = 0.08838834764831845f;  // 1/sqrt(128)
    const int nkv = (q0 + BQ) / BKV;           // causal: only tiles with k0 <= q0+127

    for (int kt = 0; kt < nkv; kt++) {
        const int k0 = kt * BKV;

        // load K (swizzled) and V (row-major) tiles
        #pragma unroll
        for (int p = 0; p < (BKV * HD) / (256 * 4); p++) {
            int idx = p * 256 + tid;
            int r = idx >> 5;
            int c = (idx & 31) * 4;
            float4 tk = *(const float4*)&K[(k0 + r) * HD + c];
            *(float4*)&Ks[swz(r, c)] = tk;
            float4 tv = *(const float4*)&V[(k0 + r) * HD + c];
            *(float4*)&Vs[r * HD + c] = tv;
        }
        __syncthreads();

        // S = Q @ K^T : each thread 8 rows (ty*8+i) x 4 cols (tx*4+j)
        float s[8][4];
        #pragma unroll
        for (int i = 0; i < 8; i++) {
            #pragma unroll
            for (int j = 0; j < 4; j++) s[i][j] = 0.0f;
        }
        #pragma unroll 2
        for (int d4 = 0; d4 < HD / 4; d4++) {
            float4 a[8];
            #pragma unroll
            for (int i = 0; i < 8; i++)
                a[i] = *(const float4*)&Qs[swz(ty * 8 + i, d4 * 4)];
            float4 b[4];
            #pragma unroll
            for (int j = 0; j < 4; j++)
                b[j] = *(const float4*)&Ks[swz(tx * 4 + j, d4 * 4)];
            #pragma unroll
            for (int i = 0; i < 8; i++) {
                #pragma unroll
                for (int j = 0; j < 4; j++) {
                    s[i][j] += a[i].x * b[j].x;
                    s[i][j] += a[i].y * b[j].y;
                    s[i][j] += a[i].z * b[j].z;
                    s[i][j] += a[i].w * b[j].w;
                }
            }
        }

        // causal mask (only the last two kv tiles touch the diagonal)
        if (kt >= nkv - 2) {
            #pragma unroll
            for (int i = 0; i < 8; i++) {
                #pragma unroll
                for (int j = 0; j < 4; j++) {
                    if (k0 + tx * 4 + j > q0 + ty * 8 + i) s[i][j] = -INFINITY;
                }
            }
        }

        // online softmax (row stats reduced across the 16 tx lanes)
        #pragma unroll
        for (int i = 0; i < 8; i++) {
            float mx = s[i][0];
            mx = fmaxf(mx, s[i][1]);
            mx = fmaxf(mx, s[i][2]);
            mx = fmaxf(mx, s[i][3]);
            #pragma unroll
            for (int off = 1; off < 16; off <<= 1)
                mx = fmaxf(mx, __shfl_xor_sync(0xffffffffu, mx, off));

            float mnew = fmaxf(m_i[i], mx * scale);
            float alpha = __expf(m_i[i] - mnew);

            float p0 = __expf(s[i][0] * scale - mnew);
            float p1 = __expf(s[i][1] * scale - mnew);
            float p2 = __expf(s[i][2] * scale - mnew);
            float p3 = __expf(s[i][3] * scale - mnew);
            float rs = p0 + p1 + p2 + p3;
            #pragma unroll
            for (int off = 1; off < 16; off <<= 1)
                rs += __shfl_xor_sync(0xffffffffu, rs, off);

            l_i[i] = l_i[i] * alpha + rs;
            m_i[i] = mnew;
            #pragma unroll
            for (int j = 0; j < 8; j++) accO[i][j] *= alpha;

            float* prow = &Ps[(ty * 8 + i) * PS_LD + tx * 4];
            prow[0] = p0; prow[1] = p1; prow[2] = p2; prow[3] = p3;
        }
        __syncthreads();

        // O += P @ V : 8 rows x 8 cols per thread (cols tx*4 and 64+tx*4)
        #pragma unroll 4
        for (int j = 0; j < BKV; j++) {
            float4 v0 = *(const float4*)&Vs[j * HD + tx * 4];
            float4 v1 = *(const float4*)&Vs[j * HD + 64 + tx * 4];
            #pragma unroll
            for (int i = 0; i < 8; i++) {
                float pv = Ps[(ty * 8 + i) * PS_LD + j];
                accO[i][0] += pv * v0.x;
                accO[i][1] += pv * v0.y;
                accO[i][2] += pv * v0.z;
                accO[i][3] += pv * v0.w;
                accO[i][4] += pv * v1.x;
                accO[i][5] += pv * v1.y;
                accO[i][6] += pv * v1.z;
                accO[i][7] += pv * v1.w;
            }
        }
        __syncthreads();
    }

    // epilogue: O /= l, write back
    #pragma unroll
    for (int i = 0; i < 8; i++) {
        float inv = 1.0f / l_i[i];
        int r = q0 + ty * 8 + i;
        float4 o0 = make_float4(accO[i][0] * inv, accO[i][1] * inv,
                                accO[i][2] * inv, accO[i][3] * inv);
        float4 o1 = make_float4(accO[i][4] * inv, accO[i][5] * inv,
                                accO[i][6] * inv, accO[i][7] * inv);
        *(float4*)&O[r * HD + tx * 4] = o0;
        *(float4*)&O[r * HD + 64 + tx * 4] = o1;
    }
}

// ---------------------------------------------------------------------------
// Launch
// ---------------------------------------------------------------------------
extern "C" void kernel_launch(void* const* d_in, const int* in_sizes, int n_in,
                              void* d_out, int out_size)
{
    const float* x    = (const float*)d_in[0];  // [4,2048,128]
    const float* qkv  = (const float*)d_in[1];  // [128, 3072]
    const float* proj = (const float*)d_in[2];  // [1024, 128]
    float* out = (float*)d_out;                 // [4,2048,128]

    float *gq, *gk, *gv, *go;
    cudaGetSymbolAddress((void**)&gq, g_q);
    cudaGetSymbolAddress((void**)&gk, g_k);
    cudaGetSymbolAddress((void**)&gv, g_v);
    cudaGetSymbolAddress((void**)&go, g_o);

    const int M = HB * SEQ;          // 8192
    const int NQKV = NH * HD;        // 1024
    const int KDIM = HD;             // 128

    // QKV projections: Y = x @ W  (Y per-head chunks are contiguous [2048,128])
    dim3 gridQKV(NQKV / 128, M / 128);
    sgemm_kernel<128,128,8,8,8><<<gridQKV, 256>>>(M, NQKV, KDIM,
        x, HD, qkv,          3 * NQKV, gq, NQKV);
    sgemm_kernel<128,128,8,8,8><<<gridQKV, 256>>>(M, NQKV, KDIM,
        x, HD, qkv + NQKV,   3 * NQKV, gk, NQKV);
    sgemm_kernel<128,128,8,8,8><<<gridQKV, 256>>>(M, NQKV, KDIM,
        x, HD, qkv + 2*NQKV, 3 * NQKV, gv, NQKV);

    // Flash attention: 32 heads x 16 q-tiles
    const int flash_smem = (BQ * HD + 2 * BKV * HD + BQ * PS_LD) * (int)sizeof(float);
    cudaFuncSetAttribute(flash_kernel,
                         cudaFuncAttributeMaxDynamicSharedMemorySize, flash_smem);
    flash_kernel<<<dim3(HEADS, SEQ / BQ), 256, flash_smem>>>(gq, gk, gv, go);

    // Output projection: out = O_flat[8192,1024] @ proj[1024,128]
    sgemm_kernel<64,128,16,4,8><<<dim3(1, M / 64), 256>>>(M, HD, NQKV,
        go, NQKV, proj, HD, out, HD);
}

// round 3
// speedup vs baseline: 1.8482x; 1.8482x over previous
#include <cuda_runtime.h>
#include <math.h>
#include <stdint.h>

// Problem constants (B=4, S=2048, H=128, NH=8)
#define HB 4
#define SEQ 2048
#define HD 128
#define NH 8
#define HEADS (HB * NH)            // 32
#define HEADELEMS (SEQ * HD)       // 262144
#define YELEMS (HB * SEQ * NH * HD) // 8388608

// Scratch (device globals: allocation-free per harness rules)
__device__ float g_q[YELEMS];
__device__ float g_k[YELEMS];
__device__ float g_v[YELEMS];
__device__ float g_o[YELEMS];

// ---------------------------------------------------------------------------
// Generic fp32 SGEMM (unchanged from round 2): C[M,N] = A[M,K] @ B[K,N]
// ---------------------------------------------------------------------------
template<int BM, int BN, int BK, int TM, int TN>
__global__ __launch_bounds__(256, 1)
void sgemm_kernel(int M, int N, int K,
                  const float* __restrict__ A, int lda,
                  const float* __restrict__ B, int ldb,
                  float* __restrict__ C, int ldc)
{
    __shared__ float As[BK][BM];
    __shared__ float Bs[BK][BN];

    const int tid = threadIdx.x;
    const int tx = tid & 15;
    const int ty = tid >> 4;
    const int row0 = blockIdx.y * BM;
    const int col0 = blockIdx.x * BN;

    constexpr int AE = (BM * BK) / 256;
    constexpr int BE = (BK * BN) / 256;
    constexpr int RG = TM / 4;
    constexpr int CG = TN / 4;

    float aReg[AE], bReg[BE];
    const float* Ab = A + (long)row0 * lda;
    const float* Bp = B + col0;

    #pragma unroll
    for (int i = 0; i < AE; i++) {
        int idx = i * 256 + tid;
        aReg[i] = Ab[(idx / BK) * lda + (idx % BK)];
    }
    #pragma unroll
    for (int i = 0; i < BE; i++) {
        int idx = i * 256 + tid;
        bReg[i] = Bp[(idx / BN) * ldb + (idx % BN)];
    }

    float acc[TM][TN];
    #pragma unroll
    for (int i = 0; i < TM; i++)
        #pragma unroll
        for (int j = 0; j < TN; j++) acc[i][j] = 0.0f;

    const int nk = K / BK;
    for (int kt = 0; kt < nk; kt++) {
        __syncthreads();
        #pragma unroll
        for (int i = 0; i < AE; i++) {
            int idx = i * 256 + tid;
            As[idx % BK][idx / BK] = aReg[i];
        }
        #pragma unroll
        for (int i = 0; i < BE; i++) {
            int idx = i * 256 + tid;
            Bs[idx / BN][idx % BN] = bReg[i];
        }
        __syncthreads();

        if (kt + 1 < nk) {
            const int k0 = (kt + 1) * BK;
            #pragma unroll
            for (int i = 0; i < AE; i++) {
                int idx = i * 256 + tid;
                aReg[i] = Ab[(idx / BK) * lda + k0 + (idx % BK)];
            }
            #pragma unroll
            for (int i = 0; i < BE; i++) {
                int idx = i * 256 + tid;
                bReg[i] = Bp[(k0 + idx / BN) * ldb + (idx % BN)];
            }
        }

        #pragma unroll
        for (int kk = 0; kk < BK; kk++) {
            float av[TM], bv[TN];
            #pragma unroll
            for (int g = 0; g < RG; g++) {
                float4 t = *(const float4*)&As[kk][g * (BM / 2) + ty * 4];
                av[g*4+0] = t.x; av[g*4+1] = t.y; av[g*4+2] = t.z; av[g*4+3] = t.w;
            }
            #pragma unroll
            for (int g = 0; g < CG; g++) {
                float4 t = *(const float4*)&Bs[kk][g * (BN / 2) + tx * 4];
                bv[g*4+0] = t.x; bv[g*4+1] = t.y; bv[g*4+2] = t.z; bv[g*4+3] = t.w;
            }
            #pragma unroll
            for (int i = 0; i < TM; i++)
                #pragma unroll
                for (int j = 0; j < TN; j++)
                    acc[i][j] += av[i] * bv[j];
        }
    }

    #pragma unroll
    for (int i = 0; i < TM; i++) {
        const int row = row0 + (i / 4) * (BM / 2) + ty * 4 + (i % 4);
        #pragma unroll
        for (int g = 0; g < CG; g++) {
            const int col = col0 + g * (BN / 2) + tx * 4;
            float4 t = make_float4(acc[i][g*4+0], acc[i][g*4+1],
                                   acc[i][g*4+2], acc[i][g*4+3]);
            *(float4*)&C[(long)row * ldc + col] = t;
        }
    }
}

// ---------------------------------------------------------------------------
// TF32 tensor-core flash attention (causal), one [2048,128] head per block-x.
// BQ=128 rows / CTA (8 warps, each owns 16 rows), BKV=64 keys per tile.
// S-phase: per warp m16 x n64 (8 n-tiles), k = 128 in 16 steps of 8.
// PV-phase: per warp m16 x n128 (16 n-tiles), k = 64 in 8 steps of 8.
// All softmax state and P rows are warp-local (no cross-warp coupling).
// Padded smem leading dims give conflict-free fragment loads:
//   Q/K/P ld=132 (4g+c banks), V ld=136 (8c+g banks).
// ---------------------------------------------------------------------------
#define BQ 128
#define BKV 64
#define LDQK 132
#define LDV 136
#define LDP 132

#define QS_OFF 0
#define KS_OFF (BQ * LDQK)                 // 16896
#define VS_OFF (KS_OFF + BKV * LDQK)       // 25344
#define PS_OFF (VS_OFF + BKV * LDV)        // 34048
#define SMEM_WORDS (PS_OFF + BQ * LDP)     // 50944

__device__ __forceinline__ uint32_t f2tf(float f) {
    uint32_t u;
    asm("cvt.rna.tf32.f32 %0, %1;" : "=r"(u) : "f"(f));
    return u;
}

__device__ __forceinline__ void mma_tf32(float c[4],
    uint32_t a0, uint32_t a1, uint32_t a2, uint32_t a3,
    uint32_t b0, uint32_t b1)
{
    asm volatile(
        "mma.sync.aligned.m16n8k8.row.col.f32.tf32.tf32.f32 "
        "{%0,%1,%2,%3}, {%4,%5,%6,%7}, {%8,%9}, {%0,%1,%2,%3};\n"
        : "+f"(c[0]), "+f"(c[1]), "+f"(c[2]), "+f"(c[3])
        : "r"(a0), "r"(a1), "r"(a2), "r"(a3), "r"(b0), "r"(b1));
}

__global__ __launch_bounds__(256, 1)
void flash_tf32_kernel(const float* __restrict__ gq, const float* __restrict__ gk,
                       const float* __restrict__ gv, float* __restrict__ go)
{
    extern __shared__ uint32_t sm[];
    uint32_t* Qs = sm + QS_OFF;
    uint32_t* Ks = sm + KS_OFF;
    uint32_t* Vs = sm + VS_OFF;
    uint32_t* Ps = sm + PS_OFF;

    const int tid  = threadIdx.x;
    const int w    = tid >> 5;       // warp 0..7
    const int lane = tid & 31;
    const int g    = lane >> 2;      // group row 0..7
    const int c4   = lane & 3;       // thread-in-group 0..3
    const int mw   = w * 16;         // warp's row base within tile

    const int hb = blockIdx.x;
    const int qt = (int)gridDim.y - 1 - (int)blockIdx.y;
    const int q0 = qt * BQ;

    const float* Q = gq + (long)hb * HEADELEMS;
    const float* K = gk + (long)hb * HEADELEMS;
    const float* V = gv + (long)hb * HEADELEMS;
    float*       O = go + (long)hb * HEADELEMS;

    const float scale = 0.08838834764831845f;  // 1/sqrt(128)

    // ---- load Q tile, pre-scaled, tf32-converted ----
    #pragma unroll
    for (int p = 0; p < (BQ * HD) / (256 * 4); p++) {
        int idx = p * 256 + tid;
        int r = idx >> 5;            // 32 float4 per row
        int c = (idx & 31) * 4;
        float4 t = *(const float4*)&Q[(q0 + r) * HD + c];
        uint4 u = make_uint4(f2tf(t.x * scale), f2tf(t.y * scale),
                             f2tf(t.z * scale), f2tf(t.w * scale));
        *(uint4*)&Qs[r * LDQK + c] = u;
    }

    // ---- accumulators / softmax state (all warp-local) ----
    float of[16][4];
    #pragma unroll
    for (int t = 0; t < 16; t++)
        #pragma unroll
        for (int j = 0; j < 4; j++) of[t][j] = 0.0f;
    float m0 = -INFINITY, m1 = -INFINITY, l0 = 0.0f, l1 = 0.0f;

    const int nkv = (q0 + BQ) / BKV;

    for (int kt = 0; kt < nkv; kt++) {
        const int k0 = kt * BKV;

        // ---- load K (ld=132) and V (ld=136) tiles, tf32-converted ----
        #pragma unroll
        for (int p = 0; p < (BKV * HD) / (256 * 4); p++) {
            int idx = p * 256 + tid;
            int r = idx >> 5;
            int c = (idx & 31) * 4;
            float4 tk = *(const float4*)&K[(k0 + r) * HD + c];
            *(uint4*)&Ks[r * LDQK + c] =
                make_uint4(f2tf(tk.x), f2tf(tk.y), f2tf(tk.z), f2tf(tk.w));
            float4 tv = *(const float4*)&V[(k0 + r) * HD + c];
            *(uint4*)&Vs[r * LDV + c] =
                make_uint4(f2tf(tv.x), f2tf(tv.y), f2tf(tv.z), f2tf(tv.w));
        }
        __syncthreads();

        // ---- S = (Q*scale) @ K^T : warp tile m16 x n64 ----
        float sf[8][4];
        #pragma unroll
        for (int t = 0; t < 8; t++)
            #pragma unroll
            for (int j = 0; j < 4; j++) sf[t][j] = 0.0f;

        #pragma unroll
        for (int k = 0; k < 16; k++) {
            const int kc = k * 8;
            uint32_t a0 = Qs[(mw + g)     * LDQK + kc + c4];
            uint32_t a1 = Qs[(mw + g + 8) * LDQK + kc + c4];
            uint32_t a2 = Qs[(mw + g)     * LDQK + kc + 4 + c4];
            uint32_t a3 = Qs[(mw + g + 8) * LDQK + kc + 4 + c4];
            #pragma unroll
            for (int t = 0; t < 8; t++) {
                uint32_t b0 = Ks[(t * 8 + g) * LDQK + kc + c4];
                uint32_t b1 = Ks[(t * 8 + g) * LDQK + kc + 4 + c4];
                mma_tf32(sf[t], a0, a1, a2, a3, b0, b1);
            }
        }

        // ---- causal mask (only tiles touching the diagonal) ----
        if (kt >= nkv - 2) {
            const int r0 = q0 + mw + g;
            const int r1 = r0 + 8;
            #pragma unroll
            for (int t = 0; t < 8; t++) {
                const int cg0 = k0 + t * 8 + c4 * 2;
                if (cg0     > r0) sf[t][0] = -INFINITY;
                if (cg0 + 1 > r0) sf[t][1] = -INFINITY;
                if (cg0     > r1) sf[t][2] = -INFINITY;
                if (cg0 + 1 > r1) sf[t][3] = -INFINITY;
            }
        }

        // ---- online softmax (rows mw+g and mw+g+8, quad-local reduce) ----
        float mx0 = -INFINITY, mx1 = -INFINITY;
        #pragma unroll
        for (int t = 0; t < 8; t++) {
            mx0 = fmaxf(mx0, fmaxf(sf[t][0], sf[t][1]));
            mx1 = fmaxf(mx1, fmaxf(sf[t][2], sf[t][3]));
        }
        mx0 = fmaxf(mx0, __shfl_xor_sync(0xffffffffu, mx0, 1));
        mx0 = fmaxf(mx0, __shfl_xor_sync(0xffffffffu, mx0, 2));
        mx1 = fmaxf(mx1, __shfl_xor_sync(0xffffffffu, mx1, 1));
        mx1 = fmaxf(mx1, __shfl_xor_sync(0xffffffffu, mx1, 2));

        const float mn0 = fmaxf(m0, mx0);
        const float mn1 = fmaxf(m1, mx1);
        const float al0 = __expf(m0 - mn0);
        const float al1 = __expf(m1 - mn1);

        float s0 = 0.0f, s1 = 0.0f;
        #pragma unroll
        for (int t = 0; t < 8; t++) {
            sf[t][0] = __expf(sf[t][0] - mn0);
            sf[t][1] = __expf(sf[t][1] - mn0);
            sf[t][2] = __expf(sf[t][2] - mn1);
            sf[t][3] = __expf(sf[t][3] - mn1);
            s0 += sf[t][0] + sf[t][1];
            s1 += sf[t][2] + sf[t][3];
        }
        s0 += __shfl_xor_sync(0xffffffffu, s0, 1);
        s0 += __shfl_xor_sync(0xffffffffu, s0, 2);
        s1 += __shfl_xor_sync(0xffffffffu, s1, 1);
        s1 += __shfl_xor_sync(0xffffffffu, s1, 2);

        l0 = l0 * al0 + s0;  m0 = mn0;
        l1 = l1 * al1 + s1;  m1 = mn1;

        #pragma unroll
        for (int t = 0; t < 16; t++) {
            of[t][0] *= al0; of[t][1] *= al0;
            of[t][2] *= al1; of[t][3] *= al1;
        }

        // ---- store P (tf32) to warp-local rows of Ps ----
        #pragma unroll
        for (int t = 0; t < 8; t++) {
            *(uint2*)&Ps[(mw + g)     * LDP + t * 8 + c4 * 2] =
                make_uint2(f2tf(sf[t][0]), f2tf(sf[t][1]));
            *(uint2*)&Ps[(mw + g + 8) * LDP + t * 8 + c4 * 2] =
                make_uint2(f2tf(sf[t][2]), f2tf(sf[t][3]));
        }
        __syncwarp();

        // ---- O += P @ V : warp tile m16 x n128 ----
        #pragma unroll
        for (int k = 0; k < 8; k++) {
            const int kc = k * 8;
            uint32_t a0 = Ps[(mw + g)     * LDP + kc + c4];
            uint32_t a1 = Ps[(mw + g + 8) * LDP + kc + c4];
            uint32_t a2 = Ps[(mw + g)     * LDP + kc + 4 + c4];
            uint32_t a3 = Ps[(mw + g + 8) * LDP + kc + 4 + c4];
            #pragma unroll
            for (int t = 0; t < 16; t++) {
                uint32_t b0 = Vs[(kc + c4)     * LDV + t * 8 + g];
                uint32_t b1 = Vs[(kc + 4 + c4) * LDV + t * 8 + g];
                mma_tf32(of[t], a0, a1, a2, a3, b0, b1);
            }
        }
        __syncthreads();   // PV done before next tile overwrites Ks/Vs
    }

    // ---- epilogue: O /= l, write out ----
    const float inv0 = 1.0f / l0;
    const float inv1 = 1.0f / l1;
    const int r0 = q0 + mw + g;
    const int r1 = r0 + 8;
    #pragma unroll
    for (int t = 0; t < 16; t++) {
        const int col = t * 8 + c4 * 2;
        *(float2*)&O[r0 * HD + col] = make_float2(of[t][0] * inv0, of[t][1] * inv0);
        *(float2*)&O[r1 * HD + col] = make_float2(of[t][2] * inv1, of[t][3] * inv1);
    }
}

// ---------------------------------------------------------------------------
// Launch
// ---------------------------------------------------------------------------
extern "C" void kernel_launch(void* const* d_in, const int* in_sizes, int n_in,
                              void* d_out, int out_size)
{
    const float* x    = (const float*)d_in[0];  // [4,2048,128]
    const float* qkv  = (const float*)d_in[1];  // [128, 3072]
    const float* proj = (const float*)d_in[2];  // [1024, 128]
    float* out = (float*)d_out;                 // [4,2048,128]

    float *gq, *gk, *gv, *go;
    cudaGetSymbolAddress((void**)&gq, g_q);
    cudaGetSymbolAddress((void**)&gk, g_k);
    cudaGetSymbolAddress((void**)&gv, g_v);
    cudaGetSymbolAddress((void**)&go, g_o);

    const int M = HB * SEQ;          // 8192
    const int NQKV = NH * HD;        // 1024
    const int KDIM = HD;             // 128

    dim3 gridQKV(NQKV / 128, M / 128);
    sgemm_kernel<128,128,8,8,8><<<gridQKV, 256>>>(M, NQKV, KDIM,
        x, HD, qkv,          3 * NQKV, gq, NQKV);
    sgemm_kernel<128,128,8,8,8><<<gridQKV, 256>>>(M, NQKV, KDIM,
        x, HD, qkv + NQKV,   3 * NQKV, gk, NQKV);
    sgemm_kernel<128,128,8,8,8><<<gridQKV, 256>>>(M, NQKV, KDIM,
        x, HD, qkv + 2*NQKV, 3 * NQKV, gv, NQKV);

    const int flash_smem = SMEM_WORDS * (int)sizeof(uint32_t);  // 203,776 B
    cudaFuncSetAttribute(flash_tf32_kernel,
                         cudaFuncAttributeMaxDynamicSharedMemorySize, flash_smem);
    flash_tf32_kernel<<<dim3(HEADS, SEQ / BQ), 256, flash_smem>>>(gq, gk, gv, go);

    sgemm_kernel<64,128,16,4,8><<<dim3(1, M / 64), 256>>>(M, HD, NQKV,
        go, NQKV, proj, HD, out, HD);
}

// round 5
// speedup vs baseline: 2.9390x; 1.5902x over previous
#include <cuda_runtime.h>
#include <math.h>
#include <stdint.h>

// Problem constants (B=4, S=2048, H=128, NH=8)
#define HB 4
#define SEQ 2048
#define HD 128
#define NH 8
#define HEADS (HB * NH)            // 32
#define HEADELEMS (SEQ * HD)       // 262144
#define YELEMS (HB * SEQ * NH * HD) // 8388608

// Scratch (device globals: allocation-free per harness rules)
__device__ float g_q[YELEMS];
__device__ float g_k[YELEMS];
__device__ float g_v[YELEMS];
__device__ float g_o[YELEMS];

__device__ __forceinline__ uint32_t f2tf(float f) {
    uint32_t u;
    asm("cvt.rna.tf32.f32 %0, %1;" : "=r"(u) : "f"(f));
    return u;
}

__device__ __forceinline__ void mma_tf32(float c[4],
    uint32_t a0, uint32_t a1, uint32_t a2, uint32_t a3,
    uint32_t b0, uint32_t b1)
{
    asm volatile(
        "mma.sync.aligned.m16n8k8.row.col.f32.tf32.tf32.f32 "
        "{%0,%1,%2,%3}, {%4,%5,%6,%7}, {%8,%9}, {%0,%1,%2,%3};\n"
        : "+f"(c[0]), "+f"(c[1]), "+f"(c[2]), "+f"(c[3])
        : "r"(a0), "r"(a1), "r"(a2), "r"(a3), "r"(b0), "r"(b1));
}

// ---------------------------------------------------------------------------
// TF32 tensor-core GEMM: C = A[M,K] @ B[K,N], row-major fp32 in/out.
// BM=128 (8 warps x m16), BK=128 per iteration, BN per template (64/128).
// Fragment scheme identical to the flash PV phase (validated round 3):
//   A smem ld=132 (banks 4g+c4), B smem ld=BN+8 (banks 8c4+g), conflict-free.
// Epilogue routes each BN-column block to one of three segment outputs
// (for the fused QKV GEMM); pass segW >= N for a single output.
// ---------------------------------------------------------------------------
template<int BN, int NKITER>
__global__ __launch_bounds__(256, 1)
void tf32_gemm_kernel(const float* __restrict__ A, int lda,
                      const float* __restrict__ B, int ldb,
                      float* __restrict__ C0, float* __restrict__ C1,
                      float* __restrict__ C2, int ldc, int segW)
{
    constexpr int BM = 128;
    constexpr int BK = 128;
    constexpr int LDA_S = 132;
    constexpr int LDB_S = BN + 8;
    constexpr int NT = BN / 8;

    extern __shared__ uint32_t smg[];
    uint32_t* As = smg;                    // BM x LDA_S
    uint32_t* Bs = smg + BM * LDA_S;       // BK x LDB_S

    const int tid  = threadIdx.x;
    const int w    = tid >> 5;
    const int lane = tid & 31;
    const int g    = lane >> 2;
    const int c4   = lane & 3;
    const int mw   = w * 16;

    const int row0 = blockIdx.y * BM;
    const int colg = blockIdx.x * BN;
    const int seg  = colg / segW;
    float* C = (seg == 0) ? C0 : ((seg == 1) ? C1 : C2);
    const int coll = colg - seg * segW;

    float acc[NT][4];
    #pragma unroll
    for (int t = 0; t < NT; t++)
        #pragma unroll
        for (int j = 0; j < 4; j++) acc[t][j] = 0.0f;

    for (int kt = 0; kt < NKITER; kt++) {
        const int k0 = kt * BK;

        // load A tile (BM x BK), tf32-converted
        #pragma unroll
        for (int p = 0; p < (BM * BK) / (256 * 4); p++) {
            int idx = p * 256 + tid;
            int r = idx >> 5;               // BK/4 = 32 float4 per row
            int c = (idx & 31) * 4;
            float4 t = *(const float4*)&A[(long)(row0 + r) * lda + k0 + c];
            *(uint4*)&As[r * LDA_S + c] =
                make_uint4(f2tf(t.x), f2tf(t.y), f2tf(t.z), f2tf(t.w));
        }
        // load B tile (BK x BN), tf32-converted
        #pragma unroll
        for (int p = 0; p < (BK * BN) / (256 * 4); p++) {
            int idx = p * 256 + tid;
            int r = idx / (BN / 4);
            int c = (idx % (BN / 4)) * 4;
            float4 t = *(const float4*)&B[(long)(k0 + r) * ldb + colg + c];
            *(uint4*)&Bs[r * LDB_S + c] =
                make_uint4(f2tf(t.x), f2tf(t.y), f2tf(t.z), f2tf(t.w));
        }
        __syncthreads();

        #pragma unroll
        for (int kcix = 0; kcix < BK / 8; kcix++) {
            const int kc = kcix * 8;
            uint32_t a0 = As[(mw + g)     * LDA_S + kc + c4];
            uint32_t a1 = As[(mw + g + 8) * LDA_S + kc + c4];
            uint32_t a2 = As[(mw + g)     * LDA_S + kc + 4 + c4];
            uint32_t a3 = As[(mw + g + 8) * LDA_S + kc + 4 + c4];
            #pragma unroll
            for (int t = 0; t < NT; t++) {
                uint32_t b0 = Bs[(kc + c4)     * LDB_S + t * 8 + g];
                uint32_t b1 = Bs[(kc + 4 + c4) * LDB_S + t * 8 + g];
                mma_tf32(acc[t], a0, a1, a2, a3, b0, b1);
            }
        }
        __syncthreads();
    }

    // epilogue
    const int r0 = row0 + mw + g;
    const int r1 = r0 + 8;
    #pragma unroll
    for (int t = 0; t < NT; t++) {
        const int col = coll + t * 8 + c4 * 2;
        *(float2*)&C[(long)r0 * ldc + col] = make_float2(acc[t][0], acc[t][1]);
        *(float2*)&C[(long)r1 * ldc + col] = make_float2(acc[t][2], acc[t][3]);
    }
}

// ---------------------------------------------------------------------------
// TF32 tensor-core flash attention (causal) — unchanged from round 3.
// ---------------------------------------------------------------------------
#define BQ 128
#define BKV 64
#define LDQK 132
#define LDV 136
#define LDP 132

#define QS_OFF 0
#define KS_OFF (BQ * LDQK)
#define VS_OFF (KS_OFF + BKV * LDQK)
#define PS_OFF (VS_OFF + BKV * LDV)
#define SMEM_WORDS (PS_OFF + BQ * LDP)

__global__ __launch_bounds__(256, 1)
void flash_tf32_kernel(const float* __restrict__ gq, const float* __restrict__ gk,
                       const float* __restrict__ gv, float* __restrict__ go)
{
    extern __shared__ uint32_t sm[];
    uint32_t* Qs = sm + QS_OFF;
    uint32_t* Ks = sm + KS_OFF;
    uint32_t* Vs = sm + VS_OFF;
    uint32_t* Ps = sm + PS_OFF;

    const int tid  = threadIdx.x;
    const int w    = tid >> 5;
    const int lane = tid & 31;
    const int g    = lane >> 2;
    const int c4   = lane & 3;
    const int mw   = w * 16;

    const int hb = blockIdx.x;
    const int qt = (int)gridDim.y - 1 - (int)blockIdx.y;
    const int q0 = qt * BQ;

    const float* Q = gq + (long)hb * HEADELEMS;
    const float* K = gk + (long)hb * HEADELEMS;
    const float* V = gv + (long)hb * HEADELEMS;
    float*       O = go + (long)hb * HEADELEMS;

    const float scale = 0.08838834764831845f;  // 1/sqrt(128)

    #pragma unroll
    for (int p = 0; p < (BQ * HD) / (256 * 4); p++) {
        int idx = p * 256 + tid;
        int r = idx >> 5;
        int c = (idx & 31) * 4;
        float4 t = *(const float4*)&Q[(q0 + r) * HD + c];
        uint4 u = make_uint4(f2tf(t.x * scale), f2tf(t.y * scale),
                             f2tf(t.z * scale), f2tf(t.w * scale));
        *(uint4*)&Qs[r * LDQK + c] = u;
    }

    float of[16][4];
    #pragma unroll
    for (int t = 0; t < 16; t++)
        #pragma unroll
        for (int j = 0; j < 4; j++) of[t][j] = 0.0f;
    float m0 = -INFINITY, m1 = -INFINITY, l0 = 0.0f, l1 = 0.0f;

    const int nkv = (q0 + BQ) / BKV;

    for (int kt = 0; kt < nkv; kt++) {
        const int k0 = kt * BKV;

        #pragma unroll
        for (int p = 0; p < (BKV * HD) / (256 * 4); p++) {
            int idx = p * 256 + tid;
            int r = idx >> 5;
            int c = (idx & 31) * 4;
            float4 tk = *(const float4*)&K[(k0 + r) * HD + c];
            *(uint4*)&Ks[r * LDQK + c] =
                make_uint4(f2tf(tk.x), f2tf(tk.y), f2tf(tk.z), f2tf(tk.w));
            float4 tv = *(const float4*)&V[(k0 + r) * HD + c];
            *(uint4*)&Vs[r * LDV + c] =
                make_uint4(f2tf(tv.x), f2tf(tv.y), f2tf(tv.z), f2tf(tv.w));
        }
        __syncthreads();

        float sf[8][4];
        #pragma unroll
        for (int t = 0; t < 8; t++)
            #pragma unroll
            for (int j = 0; j < 4; j++) sf[t][j] = 0.0f;

        #pragma unroll
        for (int k = 0; k < 16; k++) {
            const int kc = k * 8;
            uint32_t a0 = Qs[(mw + g)     * LDQK + kc + c4];
            uint32_t a1 = Qs[(mw + g + 8) * LDQK + kc + c4];
            uint32_t a2 = Qs[(mw + g)     * LDQK + kc + 4 + c4];
            uint32_t a3 = Qs[(mw + g + 8) * LDQK + kc + 4 + c4];
            #pragma unroll
            for (int t = 0; t < 8; t++) {
                uint32_t b0 = Ks[(t * 8 + g) * LDQK + kc + c4];
                uint32_t b1 = Ks[(t * 8 + g) * LDQK + kc + 4 + c4];
                mma_tf32(sf[t], a0, a1, a2, a3, b0, b1);
            }
        }

        if (kt >= nkv - 2) {
            const int r0 = q0 + mw + g;
            const int r1 = r0 + 8;
            #pragma unroll
            for (int t = 0; t < 8; t++) {
                const int cg0 = k0 + t * 8 + c4 * 2;
                if (cg0     > r0) sf[t][0] = -INFINITY;
                if (cg0 + 1 > r0) sf[t][1] = -INFINITY;
                if (cg0     > r1) sf[t][2] = -INFINITY;
                if (cg0 + 1 > r1) sf[t][3] = -INFINITY;
            }
        }

        float mx0 = -INFINITY, mx1 = -INFINITY;
        #pragma unroll
        for (int t = 0; t < 8; t++) {
            mx0 = fmaxf(mx0, fmaxf(sf[t][0], sf[t][1]));
            mx1 = fmaxf(mx1, fmaxf(sf[t][2], sf[t][3]));
        }
        mx0 = fmaxf(mx0, __shfl_xor_sync(0xffffffffu, mx0, 1));
        mx0 = fmaxf(mx0, __shfl_xor_sync(0xffffffffu, mx0, 2));
        mx1 = fmaxf(mx1, __shfl_xor_sync(0xffffffffu, mx1, 1));
        mx1 = fmaxf(mx1, __shfl_xor_sync(0xffffffffu, mx1, 2));

        const float mn0 = fmaxf(m0, mx0);
        const float mn1 = fmaxf(m1, mx1);
        const float al0 = __expf(m0 - mn0);
        const float al1 = __expf(m1 - mn1);

        float s0 = 0.0f, s1 = 0.0f;
        #pragma unroll
        for (int t = 0; t < 8; t++) {
            sf[t][0] = __expf(sf[t][0] - mn0);
            sf[t][1] = __expf(sf[t][1] - mn0);
            sf[t][2] = __expf(sf[t][2] - mn1);
            sf[t][3] = __expf(sf[t][3] - mn1);
            s0 += sf[t][0] + sf[t][1];
            s1 += sf[t][2] + sf[t][3];
        }
        s0 += __shfl_xor_sync(0xffffffffu, s0, 1);
        s0 += __shfl_xor_sync(0xffffffffu, s0, 2);
        s1 += __shfl_xor_sync(0xffffffffu, s1, 1);
        s1 += __shfl_xor_sync(0xffffffffu, s1, 2);

        l0 = l0 * al0 + s0;  m0 = mn0;
        l1 = l1 * al1 + s1;  m1 = mn1;

        #pragma unroll
        for (int t = 0; t < 16; t++) {
            of[t][0] *= al0; of[t][1] *= al0;
            of[t][2] *= al1; of[t][3] *= al1;
        }

        #pragma unroll
        for (int t = 0; t < 8; t++) {
            *(uint2*)&Ps[(mw + g)     * LDP + t * 8 + c4 * 2] =
                make_uint2(f2tf(sf[t][0]), f2tf(sf[t][1]));
            *(uint2*)&Ps[(mw + g + 8) * LDP + t * 8 + c4 * 2] =
                make_uint2(f2tf(sf[t][2]), f2tf(sf[t][3]));
        }
        __syncwarp();

        #pragma unroll
        for (int k = 0; k < 8; k++) {
            const int kc = k * 8;
            uint32_t a0 = Ps[(mw + g)     * LDP + kc + c4];
            uint32_t a1 = Ps[(mw + g + 8) * LDP + kc + c4];
            uint32_t a2 = Ps[(mw + g)     * LDP + kc + 4 + c4];
            uint32_t a3 = Ps[(mw + g + 8) * LDP + kc + 4 + c4];
            #pragma unroll
            for (int t = 0; t < 16; t++) {
                uint32_t b0 = Vs[(kc + c4)     * LDV + t * 8 + g];
                uint32_t b1 = Vs[(kc + 4 + c4) * LDV + t * 8 + g];
                mma_tf32(of[t], a0, a1, a2, a3, b0, b1);
            }
        }
        __syncthreads();
    }

    const float inv0 = 1.0f / l0;
    const float inv1 = 1.0f / l1;
    const int r0 = q0 + mw + g;
    const int r1 = r0 + 8;
    #pragma unroll
    for (int t = 0; t < 16; t++) {
        const int col = t * 8 + c4 * 2;
        *(float2*)&O[r0 * HD + col] = make_float2(of[t][0] * inv0, of[t][1] * inv0);
        *(float2*)&O[r1 * HD + col] = make_float2(of[t][2] * inv1, of[t][3] * inv1);
    }
}

// ---------------------------------------------------------------------------
// Launch
// ---------------------------------------------------------------------------
extern "C" void kernel_launch(void* const* d_in, const int* in_sizes, int n_in,
                              void* d_out, int out_size)
{
    const float* x    = (const float*)d_in[0];  // [4,2048,128]
    const float* qkv  = (const float*)d_in[1];  // [128, 3072]
    const float* proj = (const float*)d_in[2];  // [1024, 128]
    float* out = (float*)d_out;                 // [4,2048,128]

    float *gq, *gk, *gv, *go;
    cudaGetSymbolAddress((void**)&gq, g_q);
    cudaGetSymbolAddress((void**)&gk, g_k);
    cudaGetSymbolAddress((void**)&gv, g_v);
    cudaGetSymbolAddress((void**)&go, g_o);

    const int M = HB * SEQ;          // 8192
    const int NQKV = NH * HD;        // 1024

    // Fused QKV: [8192,128] @ [128,3072], K=128 (single k-tile), split epilogue
    const int qkv_smem = (128 * 132 + 128 * 136) * (int)sizeof(uint32_t);  // 137,216
    cudaFuncSetAttribute(tf32_gemm_kernel<128, 1>,
                         cudaFuncAttributeMaxDynamicSharedMemorySize, qkv_smem);
    tf32_gemm_kernel<128, 1><<<dim3(3 * NQKV / 128, M / 128), 256, qkv_smem>>>(
        x, HD, qkv, 3 * NQKV, gq, gk, gv, NQKV, NQKV);

    // Flash attention: 32 heads x 16 q-tiles
    const int flash_smem = SMEM_WORDS * (int)sizeof(uint32_t);  // 203,776 B
    cudaFuncSetAttribute(flash_tf32_kernel,
                         cudaFuncAttributeMaxDynamicSharedMemorySize, flash_smem);
    flash_tf32_kernel<<<dim3(HEADS, SEQ / BQ), 256, flash_smem>>>(gq, gk, gv, go);

    // Projection: [8192,1024] @ [1024,128], BN=64, 8 k-iterations
    const int proj_smem = (128 * 132 + 128 * 72) * (int)sizeof(uint32_t);  // 104,448
    cudaFuncSetAttribute(tf32_gemm_kernel<64, 8>,
                         cudaFuncAttributeMaxDynamicSharedMemorySize, proj_smem);
    tf32_gemm_kernel<64, 8><<<dim3(HD / 64, M / 128), 256, proj_smem>>>(
        go, NQKV, proj, HD, out, out, out, HD, 1 << 30);
}

// round 6
// speedup vs baseline: 3.1967x; 1.0877x over previous
#include <cuda_runtime.h>
#include <math.h>
#include <stdint.h>

// Problem constants (B=4, S=2048, H=128, NH=8)
#define HB 4
#define SEQ 2048
#define HD 128
#define NH 8
#define HEADS (HB * NH)            // 32
#define HEADELEMS (SEQ * HD)       // 262144
#define YELEMS (HB * SEQ * NH * HD) // 8388608

// Scratch (device globals: allocation-free per harness rules)
__device__ float g_q[YELEMS];
__device__ float g_k[YELEMS];
__device__ float g_v[YELEMS];
__device__ float g_o[YELEMS];

__device__ __forceinline__ uint32_t f2tf(float f) {
    uint32_t u;
    asm("cvt.rna.tf32.f32 %0, %1;" : "=r"(u) : "f"(f));
    return u;
}

__device__ __forceinline__ void mma_tf32(float c[4],
    uint32_t a0, uint32_t a1, uint32_t a2, uint32_t a3,
    uint32_t b0, uint32_t b1)
{
    asm volatile(
        "mma.sync.aligned.m16n8k8.row.col.f32.tf32.tf32.f32 "
        "{%0,%1,%2,%3}, {%4,%5,%6,%7}, {%8,%9}, {%0,%1,%2,%3};\n"
        : "+f"(c[0]), "+f"(c[1]), "+f"(c[2]), "+f"(c[3])
        : "r"(a0), "r"(a1), "r"(a2), "r"(a3), "r"(b0), "r"(b1));
}

// ---------------------------------------------------------------------------
// TF32 tensor-core GEMM (unchanged from round 5).
// ---------------------------------------------------------------------------
template<int BN, int NKITER>
__global__ __launch_bounds__(256, 1)
void tf32_gemm_kernel(const float* __restrict__ A, int lda,
                      const float* __restrict__ B, int ldb,
                      float* __restrict__ C0, float* __restrict__ C1,
                      float* __restrict__ C2, int ldc, int segW)
{
    constexpr int BM = 128;
    constexpr int BK = 128;
    constexpr int LDA_S = 132;
    constexpr int LDB_S = BN + 8;
    constexpr int NT = BN / 8;

    extern __shared__ uint32_t smg[];
    uint32_t* As = smg;
    uint32_t* Bs = smg + BM * LDA_S;

    const int tid  = threadIdx.x;
    const int w    = tid >> 5;
    const int lane = tid & 31;
    const int g    = lane >> 2;
    const int c4   = lane & 3;
    const int mw   = w * 16;

    const int row0 = blockIdx.y * BM;
    const int colg = blockIdx.x * BN;
    const int seg  = colg / segW;
    float* C = (seg == 0) ? C0 : ((seg == 1) ? C1 : C2);
    const int coll = colg - seg * segW;

    float acc[NT][4];
    #pragma unroll
    for (int t = 0; t < NT; t++)
        #pragma unroll
        for (int j = 0; j < 4; j++) acc[t][j] = 0.0f;

    for (int kt = 0; kt < NKITER; kt++) {
        const int k0 = kt * BK;

        #pragma unroll
        for (int p = 0; p < (BM * BK) / (256 * 4); p++) {
            int idx = p * 256 + tid;
            int r = idx >> 5;
            int c = (idx & 31) * 4;
            float4 t = *(const float4*)&A[(long)(row0 + r) * lda + k0 + c];
            *(uint4*)&As[r * LDA_S + c] =
                make_uint4(f2tf(t.x), f2tf(t.y), f2tf(t.z), f2tf(t.w));
        }
        #pragma unroll
        for (int p = 0; p < (BK * BN) / (256 * 4); p++) {
            int idx = p * 256 + tid;
            int r = idx / (BN / 4);
            int c = (idx % (BN / 4)) * 4;
            float4 t = *(const float4*)&B[(long)(k0 + r) * ldb + colg + c];
            *(uint4*)&Bs[r * LDB_S + c] =
                make_uint4(f2tf(t.x), f2tf(t.y), f2tf(t.z), f2tf(t.w));
        }
        __syncthreads();

        #pragma unroll
        for (int kcix = 0; kcix < BK / 8; kcix++) {
            const int kc = kcix * 8;
            uint32_t a0 = As[(mw + g)     * LDA_S + kc + c4];
            uint32_t a1 = As[(mw + g + 8) * LDA_S + kc + c4];
            uint32_t a2 = As[(mw + g)     * LDA_S + kc + 4 + c4];
            uint32_t a3 = As[(mw + g + 8) * LDA_S + kc + 4 + c4];
            #pragma unroll
            for (int t = 0; t < NT; t++) {
                uint32_t b0 = Bs[(kc + c4)     * LDB_S + t * 8 + g];
                uint32_t b1 = Bs[(kc + 4 + c4) * LDB_S + t * 8 + g];
                mma_tf32(acc[t], a0, a1, a2, a3, b0, b1);
            }
        }
        __syncthreads();
    }

    const int r0 = row0 + mw + g;
    const int r1 = r0 + 8;
    #pragma unroll
    for (int t = 0; t < NT; t++) {
        const int col = coll + t * 8 + c4 * 2;
        *(float2*)&C[(long)r0 * ldc + col] = make_float2(acc[t][0], acc[t][1]);
        *(float2*)&C[(long)r1 * ldc + col] = make_float2(acc[t][2], acc[t][3]);
    }
}

// ---------------------------------------------------------------------------
// TF32 flash attention v2: pair-interleaved smem (all fragment loads LDS.64)
// + register prefetch double-buffering of K/V tiles.
//
// Pair layout (within-row, Q/K/P): 8-col chunk stored as
//   [x0,x4,x1,x5,x2,x6,x3,x7]  -> word(c) = (c&~7) + 2*(c&3) + ((c>>2)&1)
// so the tf32 fragment pair (k=c4, k=c4+4) is one aligned LDS.64.
// V pair layout (across-row): Vp[(r>>3)*4+(r&3)][2*col + ((r>>2)&1)]
// so the B pair (rows kc+c4, kc+4+c4; col n) is one aligned LDS.64.
// Leading dims 136/264/72 are all ==8 mod 32: each 16-lane LDS.64 phase
// covers all 32 banks exactly once (conflict-free).
// ---------------------------------------------------------------------------
#define BQ 128
#define BKV 64
#define LDQ 136
#define LDK 136
#define LDVP 264
#define LDP 72

#define QS_OFF 0
#define KS_OFF (BQ * LDQ)                    // 17408
#define VP_OFF (KS_OFF + BKV * LDK)          // 26112
#define PS_OFF (VP_OFF + 32 * LDVP)          // 34560
#define SMEM_WORDS (PS_OFF + BQ * LDP)       // 43776 words = 175104 B

__global__ __launch_bounds__(256, 1)
void flash_tf32_kernel(const float* __restrict__ gq, const float* __restrict__ gk,
                       const float* __restrict__ gv, float* __restrict__ go)
{
    extern __shared__ uint32_t sm[];
    uint32_t* Qs = sm + QS_OFF;
    uint32_t* Ks = sm + KS_OFF;
    uint32_t* Vp = sm + VP_OFF;
    uint32_t* Ps = sm + PS_OFF;

    const int tid  = threadIdx.x;
    const int lane = tid & 31;
    const int g    = lane >> 2;
    const int c4   = lane & 3;
    const int mw   = (tid >> 5) * 16;

    const int hb = blockIdx.x;
    const int qt = (int)gridDim.y - 1 - (int)blockIdx.y;
    const int q0 = qt * BQ;

    const float* Q = gq + (long)hb * HEADELEMS;
    const float* K = gk + (long)hb * HEADELEMS;
    const float* V = gv + (long)hb * HEADELEMS;
    float*       O = go + (long)hb * HEADELEMS;

    const float scale = 0.08838834764831845f;  // 1/sqrt(128)

    // ---- stage Q (pre-scaled) into pair layout: 8 chunks/thread ----
    #pragma unroll
    for (int t8 = 0; t8 < 8; t8++) {
        int cid = t8 * 256 + tid;
        int r = cid >> 4, ch = cid & 15;
        const float* src = &Q[(q0 + r) * HD + ch * 8];
        float4 a = *(const float4*)src;
        float4 b = *(const float4*)(src + 4);
        uint32_t* dst = &Qs[r * LDQ + ch * 8];
        *(uint4*)dst = make_uint4(f2tf(a.x * scale), f2tf(b.x * scale),
                                  f2tf(a.y * scale), f2tf(b.y * scale));
        *(uint4*)(dst + 4) = make_uint4(f2tf(a.z * scale), f2tf(b.z * scale),
                                        f2tf(a.w * scale), f2tf(b.w * scale));
    }

    // V loader mapping: thread owns column vc, rows [vk0, vk0+32)
    const int vc  = tid & 127;
    const int vk0 = (tid >> 7) * 32;

    const int nkv = (q0 + BQ) / BKV;

    // ---- prime tile 0 ----
    float4 ka[4], kb[4];
    float  vr[32];
    {
        #pragma unroll
        for (int t4 = 0; t4 < 4; t4++) {
            int cid = t4 * 256 + tid;
            int r = cid >> 4, ch = cid & 15;
            const float* src = &K[r * HD + ch * 8];
            ka[t4] = *(const float4*)src;
            kb[t4] = *(const float4*)(src + 4);
        }
        #pragma unroll
        for (int i = 0; i < 32; i++)
            vr[i] = V[(vk0 + i) * HD + vc];

        #pragma unroll
        for (int t4 = 0; t4 < 4; t4++) {
            int cid = t4 * 256 + tid;
            int r = cid >> 4, ch = cid & 15;
            uint32_t* dst = &Ks[r * LDK + ch * 8];
            *(uint4*)dst = make_uint4(f2tf(ka[t4].x), f2tf(kb[t4].x),
                                      f2tf(ka[t4].y), f2tf(kb[t4].y));
            *(uint4*)(dst + 4) = make_uint4(f2tf(ka[t4].z), f2tf(kb[t4].z),
                                            f2tf(ka[t4].w), f2tf(kb[t4].w));
        }
        #pragma unroll
        for (int i = 0; i < 32; i++) {
            int r = vk0 + i;
            Vp[((r >> 3) * 4 + (r & 3)) * LDVP + 2 * vc + ((r >> 2) & 1)] = f2tf(vr[i]);
        }
    }
    __syncthreads();

    float of[16][4];
    #pragma unroll
    for (int t = 0; t < 16; t++)
        #pragma unroll
        for (int j = 0; j < 4; j++) of[t][j] = 0.0f;
    float m0 = -INFINITY, m1 = -INFINITY, l0 = 0.0f, l1 = 0.0f;

    const int poslo = ((c4 & 1) << 2) | (c4 >> 1);   // P pair position for col 2*c4

    for (int kt = 0; kt < nkv; kt++) {
        const bool more = (kt + 1 < nkv);

        // ---- prefetch next K tile into registers ----
        if (more) {
            const int kn = (kt + 1) * BKV;
            #pragma unroll
            for (int t4 = 0; t4 < 4; t4++) {
                int cid = t4 * 256 + tid;
                int r = cid >> 4, ch = cid & 15;
                const float* src = &K[(kn + r) * HD + ch * 8];
                ka[t4] = *(const float4*)src;
                kb[t4] = *(const float4*)(src + 4);
            }
        }

        // ---- S = (Q*scale) @ K^T : warp tile m16 x n64, all LDS.64 ----
        float sf[8][4];
        #pragma unroll
        for (int t = 0; t < 8; t++)
            #pragma unroll
            for (int j = 0; j < 4; j++) sf[t][j] = 0.0f;

        #pragma unroll
        for (int k = 0; k < 16; k++) {
            const int kc = k * 8;
            uint2 qa = *(const uint2*)&Qs[(mw + g)     * LDQ + kc + 2 * c4]; // a0,a2
            uint2 qb = *(const uint2*)&Qs[(mw + g + 8) * LDQ + kc + 2 * c4]; // a1,a3
            #pragma unroll
            for (int t = 0; t < 8; t++) {
                uint2 kbf = *(const uint2*)&Ks[(t * 8 + g) * LDK + kc + 2 * c4];
                mma_tf32(sf[t], qa.x, qb.x, qa.y, qb.y, kbf.x, kbf.y);
            }
        }

        // ---- causal mask (tiles touching the diagonal) ----
        if (kt >= nkv - 2) {
            const int k0 = kt * BKV;
            const int r0 = q0 + mw + g;
            const int r1 = r0 + 8;
            #pragma unroll
            for (int t = 0; t < 8; t++) {
                const int cg0 = k0 + t * 8 + c4 * 2;
                if (cg0     > r0) sf[t][0] = -INFINITY;
                if (cg0 + 1 > r0) sf[t][1] = -INFINITY;
                if (cg0     > r1) sf[t][2] = -INFINITY;
                if (cg0 + 1 > r1) sf[t][3] = -INFINITY;
            }
        }

        __syncthreads();   // all warps done reading Ks

        // ---- store prefetched K into Ks (pair layout) ----
        if (more) {
            #pragma unroll
            for (int t4 = 0; t4 < 4; t4++) {
                int cid = t4 * 256 + tid;
                int r = cid >> 4, ch = cid & 15;
                uint32_t* dst = &Ks[r * LDK + ch * 8];
                *(uint4*)dst = make_uint4(f2tf(ka[t4].x), f2tf(kb[t4].x),
                                          f2tf(ka[t4].y), f2tf(kb[t4].y));
                *(uint4*)(dst + 4) = make_uint4(f2tf(ka[t4].z), f2tf(kb[t4].z),
                                                f2tf(ka[t4].w), f2tf(kb[t4].w));
            }
        }

        // ---- online softmax (quad-local reduce) ----
        float mx0 = -INFINITY, mx1 = -INFINITY;
        #pragma unroll
        for (int t = 0; t < 8; t++) {
            mx0 = fmaxf(mx0, fmaxf(sf[t][0], sf[t][1]));
            mx1 = fmaxf(mx1, fmaxf(sf[t][2], sf[t][3]));
        }
        mx0 = fmaxf(mx0, __shfl_xor_sync(0xffffffffu, mx0, 1));
        mx0 = fmaxf(mx0, __shfl_xor_sync(0xffffffffu, mx0, 2));
        mx1 = fmaxf(mx1, __shfl_xor_sync(0xffffffffu, mx1, 1));
        mx1 = fmaxf(mx1, __shfl_xor_sync(0xffffffffu, mx1, 2));

        const float mn0 = fmaxf(m0, mx0);
        const float mn1 = fmaxf(m1, mx1);
        const float al0 = __expf(m0 - mn0);
        const float al1 = __expf(m1 - mn1);

        float s0 = 0.0f, s1 = 0.0f;
        #pragma unroll
        for (int t = 0; t < 8; t++) {
            sf[t][0] = __expf(sf[t][0] - mn0);
            sf[t][1] = __expf(sf[t][1] - mn0);
            sf[t][2] = __expf(sf[t][2] - mn1);
            sf[t][3] = __expf(sf[t][3] - mn1);
            s0 += sf[t][0] + sf[t][1];
            s1 += sf[t][2] + sf[t][3];
        }
        s0 += __shfl_xor_sync(0xffffffffu, s0, 1);
        s0 += __shfl_xor_sync(0xffffffffu, s0, 2);
        s1 += __shfl_xor_sync(0xffffffffu, s1, 1);
        s1 += __shfl_xor_sync(0xffffffffu, s1, 2);

        l0 = l0 * al0 + s0;  m0 = mn0;
        l1 = l1 * al1 + s1;  m1 = mn1;

        #pragma unroll
        for (int t = 0; t < 16; t++) {
            of[t][0] *= al0; of[t][1] *= al0;
            of[t][2] *= al1; of[t][3] *= al1;
        }

        // ---- store P in pair layout (warp-local rows) ----
        #pragma unroll
        for (int t = 0; t < 8; t++) {
            uint32_t* p0 = &Ps[(mw + g)     * LDP + t * 8 + poslo];
            uint32_t* p1 = &Ps[(mw + g + 8) * LDP + t * 8 + poslo];
            p0[0] = f2tf(sf[t][0]);  p0[2] = f2tf(sf[t][1]);
            p1[0] = f2tf(sf[t][2]);  p1[2] = f2tf(sf[t][3]);
        }
        __syncwarp();

        // ---- prefetch next V tile into registers ----
        if (more) {
            const int kn = (kt + 1) * BKV;
            #pragma unroll
            for (int i = 0; i < 32; i++)
                vr[i] = V[(kn + vk0 + i) * HD + vc];
        }

        // ---- O += P @ V : warp tile m16 x n128, all LDS.64 ----
        #pragma unroll
        for (int k = 0; k < 8; k++) {
            const int kc = k * 8;
            uint2 pa = *(const uint2*)&Ps[(mw + g)     * LDP + kc + 2 * c4];
            uint2 pb = *(const uint2*)&Ps[(mw + g + 8) * LDP + kc + 2 * c4];
            #pragma unroll
            for (int t = 0; t < 16; t++) {
                uint2 vb = *(const uint2*)&Vp[(k * 4 + c4) * LDVP + 2 * (t * 8 + g)];
                mma_tf32(of[t], pa.x, pb.x, pa.y, pb.y, vb.x, vb.y);
            }
        }

        __syncthreads();   // all warps done reading Vp (and orders Ks stores)

        // ---- store prefetched V into Vp (pair layout) ----
        if (more) {
            #pragma unroll
            for (int i = 0; i < 32; i++) {
                int r = vk0 + i;
                Vp[((r >> 3) * 4 + (r & 3)) * LDVP + 2 * vc + ((r >> 2) & 1)] = f2tf(vr[i]);
            }
        }
    }

    // ---- epilogue ----
    const float inv0 = 1.0f / l0;
    const float inv1 = 1.0f / l1;
    const int r0 = q0 + mw + g;
    const int r1 = r0 + 8;
    #pragma unroll
    for (int t = 0; t < 16; t++) {
        const int col = t * 8 + c4 * 2;
        *(float2*)&O[r0 * HD + col] = make_float2(of[t][0] * inv0, of[t][1] * inv0);
        *(float2*)&O[r1 * HD + col] = make_float2(of[t][2] * inv1, of[t][3] * inv1);
    }
}

// ---------------------------------------------------------------------------
// Launch
// ---------------------------------------------------------------------------
extern "C" void kernel_launch(void* const* d_in, const int* in_sizes, int n_in,
                              void* d_out, int out_size)
{
    const float* x    = (const float*)d_in[0];  // [4,2048,128]
    const float* qkv  = (const float*)d_in[1];  // [128, 3072]
    const float* proj = (const float*)d_in[2];  // [1024, 128]
    float* out = (float*)d_out;                 // [4,2048,128]

    float *gq, *gk, *gv, *go;
    cudaGetSymbolAddress((void**)&gq, g_q);
    cudaGetSymbolAddress((void**)&gk, g_k);
    cudaGetSymbolAddress((void**)&gv, g_v);
    cudaGetSymbolAddress((void**)&go, g_o);

    const int M = HB * SEQ;          // 8192
    const int NQKV = NH * HD;        // 1024

    // Fused QKV: [8192,128] @ [128,3072], K=128 single tile, split epilogue
    const int qkv_smem = (128 * 132 + 128 * 136) * (int)sizeof(uint32_t);
    cudaFuncSetAttribute(tf32_gemm_kernel<128, 1>,
                         cudaFuncAttributeMaxDynamicSharedMemorySize, qkv_smem);
    tf32_gemm_kernel<128, 1><<<dim3(3 * NQKV / 128, M / 128), 256, qkv_smem>>>(
        x, HD, qkv, 3 * NQKV, gq, gk, gv, NQKV, NQKV);

    // Flash attention: 32 heads x 16 q-tiles
    const int flash_smem = SMEM_WORDS * (int)sizeof(uint32_t);  // 175,104 B
    cudaFuncSetAttribute(flash_tf32_kernel,
                         cudaFuncAttributeMaxDynamicSharedMemorySize, flash_smem);
    flash_tf32_kernel<<<dim3(HEADS, SEQ / BQ), 256, flash_smem>>>(gq, gk, gv, go);

    // Projection: [8192,1024] @ [1024,128]
    const int proj_smem = (128 * 132 + 128 * 72) * (int)sizeof(uint32_t);
    cudaFuncSetAttribute(tf32_gemm_kernel<64, 8>,
                         cudaFuncAttributeMaxDynamicSharedMemorySize, proj_smem);
    tf32_gemm_kernel<64, 8><<<dim3(HD / 64, M / 128), 256, proj_smem>>>(
        go, NQKV, proj, HD, out, out, out, HD, 1 << 30);
}